// round 8
// baseline (speedup 1.0000x reference)
#include <cuda_runtime.h>

// Unfold (im2col): x[16,96,56,56] f32, 3x3 window, pad 1
// out[(bc*9 + ki*3+kj)*3136 + h*56+w] = x_pad[bc][h+ki][w+kj]
//
// v8: 8-wide per thread using Blackwell 256-bit stores (st.global.cs.v8.f32,
// sm_100a). Per thread: 6 LDG.128 (3 rows x 2), halos via shuffle, then
// 9 STG.256 streaming stores -- half the store instructions of v3 for the
// same bytes. .cs retained (keeps 19MB input L2-resident; .wb lost 16%).

#define B_ 16
#define C_ 96
#define H_ 56
#define W_ 56
#define HW_ (H_ * W_)        // 3136
#define HW8_ (HW_ / 8)       // 392
#define NTHREADS_ (B_ * C_ * HW8_)   // 602,112 = 2352 * 256 exactly

__device__ __forceinline__ void stg256_cs(float* p, const float* v) {
    asm volatile(
        "st.global.cs.v8.f32 [%0], {%1,%2,%3,%4,%5,%6,%7,%8};"
        :: "l"(p), "f"(v[0]), "f"(v[1]), "f"(v[2]), "f"(v[3]),
           "f"(v[4]), "f"(v[5]), "f"(v[6]), "f"(v[7])
        : "memory");
}

__global__ __launch_bounds__(256) void unfold_kernel(
    const float* __restrict__ x, float* __restrict__ out)
{
    int tid  = blockIdx.x * 256 + threadIdx.x;   // grid exact, no guard
    int lane = threadIdx.x & 31;

    int p8 = tid % HW8_;
    int bc = tid / HW8_;
    int p  = p8 * 8;
    int h  = p / W_;
    int w  = p - h * W_;      // multiple of 8

    const float* base  = x   + (size_t)bc * HW_;
    float*       obase = out + (size_t)bc * 9 * HW_ + p;

    #pragma unroll
    for (int r = 0; r < 3; r++) {
        int  sh = h + r - 1;
        bool ok = (sh >= 0) & (sh < H_);
        const float* rp = base + sh * W_ + w;

        float4 m0 = make_float4(0.f, 0.f, 0.f, 0.f);
        float4 m1 = make_float4(0.f, 0.f, 0.f, 0.f);
        if (ok) {
            m0 = *reinterpret_cast<const float4*>(rp);       // predicated LDG.128
            m1 = *reinterpret_cast<const float4*>(rp + 4);
        }

        // halo from neighbor lanes (converged shuffles, full mask)
        float left  = __shfl_up_sync(0xffffffffu, m1.w, 1);
        float right = __shfl_down_sync(0xffffffffu, m0.x, 1);

        // warp-boundary lanes fall back to a scalar load (rare: 2/warp/row)
        if (lane == 0  && ok && w > 0)      left  = __ldg(rp - 1);
        if (lane == 31 && ok && w + 8 < W_) right = __ldg(rp + 8);

        // image-edge padding (also discards stale cross-row shuffle values)
        if (w == 0)       left  = 0.f;
        if (w + 8 >= W_)  right = 0.f;

        float a[10];
        a[0] = left;
        a[1] = m0.x; a[2] = m0.y; a[3] = m0.z; a[4] = m0.w;
        a[5] = m1.x; a[6] = m1.y; a[7] = m1.z; a[8] = m1.w;
        a[9] = right;

        float* o = obase + (size_t)(r * 3) * HW_;
        stg256_cs(o,           a + 0);   // kj=0: [w-1 .. w+6]
        stg256_cs(o + HW_,     a + 1);   // kj=1: [w   .. w+7]
        stg256_cs(o + 2 * HW_, a + 2);   // kj=2: [w+1 .. w+8]
    }
}

extern "C" void kernel_launch(void* const* d_in, const int* in_sizes, int n_in,
                              void* d_out, int out_size)
{
    const float* x = (const float*)d_in[0];
    float* out = (float*)d_out;
    unfold_kernel<<<NTHREADS_ / 256, 256>>>(x, out);
}

// round 9
// speedup vs baseline: 1.2000x; 1.2000x over previous
#include <cuda_runtime.h>

// Unfold (im2col): x[16,96,56,56] f32, 3x3 window, pad 1
// out[(bc*9 + ki*3+kj)*3136 + h*56+w] = x_pad[bc][h+ki][w+kj]
//
// FINAL (= R2 kernel, best of 8 variants at 30.72us):
// One thread = (bc, h, w4): stages 3 input rows (1 aligned LDG.128 + 2
// predicated edge scalars each), emits 9 streaming STG.128.
//
// Why this is the floor: 173MB written per call / 30.7us = 5.6 TB/s
// write-only HBM sustained; __stcs keeps the 19MB input (9x reuse)
// L2-resident across graph replays. Varied and rejected: TMA bulk stores
// (36.9), .wb policy (35.7), 256-bit stores (36.9), 4-row amortization
// (32.9), warp-shuffle halos (30.75, tied). No on-chip pipe exceeds 62%
// in any variant -- DRAM write wall.

#define B_ 16
#define C_ 96
#define H_ 56
#define W_ 56
#define HW_ (H_ * W_)        // 3136
#define HW4_ (HW_ / 4)       // 784
#define NTHREADS_ (B_ * C_ * HW4_)   // 1,204,224 = 4704 * 256 exactly

__global__ __launch_bounds__(256) void unfold_kernel(
    const float* __restrict__ x, float* __restrict__ out)
{
    int tid = blockIdx.x * 256 + threadIdx.x;   // grid is exact, no guard

    int p4 = tid % HW4_;
    int bc = tid / HW4_;
    int p  = p4 * 4;
    int h  = p / W_;
    int w  = p - h * W_;      // multiple of 4

    const float* base = x + (size_t)bc * HW_;

    // Stage 3 rows x 6 cols: [w-1, w, w+1, w+2, w+3, w+4]
    float rv[3][6];
    #pragma unroll
    for (int r = 0; r < 3; r++) {
        int sh = h + r - 1;
        if (sh >= 0 && sh < H_) {
            const float* rp = base + sh * W_;
            float4 m = *reinterpret_cast<const float4*>(rp + w);   // aligned
            rv[r][1] = m.x; rv[r][2] = m.y; rv[r][3] = m.z; rv[r][4] = m.w;
            rv[r][0] = (w > 0)        ? __ldg(rp + w - 1) : 0.f;
            rv[r][5] = (w + 4 < W_)   ? __ldg(rp + w + 4) : 0.f;
        } else {
            #pragma unroll
            for (int i = 0; i < 6; i++) rv[r][i] = 0.f;
        }
    }

    // 9 streaming stores: out[(bc*9 + r*3+kj)*HW_ + p .. +3]
    float* obase = out + (size_t)bc * 9 * HW_ + p;
    #pragma unroll
    for (int r = 0; r < 3; r++) {
        #pragma unroll
        for (int kj = 0; kj < 3; kj++) {
            float4 v = make_float4(rv[r][kj], rv[r][kj + 1],
                                   rv[r][kj + 2], rv[r][kj + 3]);
            __stcs(reinterpret_cast<float4*>(obase + (r * 3 + kj) * HW_), v);
        }
    }
}

extern "C" void kernel_launch(void* const* d_in, const int* in_sizes, int n_in,
                              void* d_out, int out_size)
{
    const float* x = (const float*)d_in[0];
    float* out = (float*)d_out;
    unfold_kernel<<<NTHREADS_ / 256, 256>>>(x, out);
}